// round 9
// baseline (speedup 1.0000x reference)
#include <cuda_runtime.h>

#define NN 4
#define C  64
#define H  160
#define W  320
#define DISP 48
#define G  8
#define HW (H*W)
#define ROWB 32                        // 8 floats per w position (one group)
#define SMEM_BYTES (W * ROWB)          // 10KB

// XOR swizzle, 16B chunks, 32B rows.
// Compute lanes step w by 4 (addr step 128B): chunk = (w>>2)&7 steps 1/lane
// -> 8 distinct 16B chunks per 8-lane LDS.128 phase -> conflict-free.
// Staging lanes step w by 1: chunk walks {0,2,4,6,1,3,5,7} over 8 lanes
// -> conflict-free STS.128 too.
__device__ __forceinline__ unsigned sw_off(int w, int colbyte) {
    unsigned off = (unsigned)(w * ROWB + colbyte);
    off ^= (((unsigned)w >> 2) & 7u) << 4;
    return off;
}

// dot of output j with ring slot s; two independent 4-chains + add.
#define DOT(j, s)                                                             \
    ((lw[0][j]*ra[s].x + lw[1][j]*ra[s].y + lw[2][j]*ra[s].z + lw[3][j]*ra[s].w) + \
     (lw[4][j]*rb[s].x + lw[5][j]*rb[s].y + lw[6][j]*rb[s].z + lw[7][j]*rb[s].w))

__global__ __launch_bounds__(80, 10)
void gwc_kernel(const float* __restrict__ lg,
                const float* __restrict__ rg,
                float* __restrict__ out) {
    __shared__ __align__(16) char rS[SMEM_BYTES];

    const int h   = blockIdx.x;
    const int n   = blockIdx.y;
    const int g   = blockIdx.z;
    const int tid = threadIdx.x;
    const int w0  = tid * 4;             // this thread's 4 output columns

    // ---- l channels: 8 contiguous LDG.128, issued before staging ----
    const float* lp = lg + ((n * C + g * 8) * H + h) * W + w0;
    float lw[8][4];
    #pragma unroll
    for (int c = 0; c < 8; ++c) {
        float4 t = *(const float4*)(lp + c * HW);
        lw[c][0] = t.x; lw[c][1] = t.y; lw[c][2] = t.z; lw[c][3] = t.w;
    }

    // ---- Stage 8 r channels, transposed [w][c], swizzled ----
    // 640 float4 items, 8 per thread: gather 4 coalesced scalar LDG + STS.128.
    {
        const float* rbase = rg + ((n * C + g * 8) * H + h) * W;
        #pragma unroll
        for (int k = 0; k < 8; ++k) {
            int i  = tid + k * 80;
            int w  = i % W;
            int c4 = (i / W) * 4;        // 0 or 4
            int gb = c4 * HW + w;
            float4 rv;
            rv.x = rbase[gb];
            rv.y = rbase[gb + HW];
            rv.z = rbase[gb + 2 * HW];
            rv.w = rbase[gb + 3 * HW];
            *(float4*)(rS + sw_off(w, c4 * 4)) = rv;
        }
    }
    __syncthreads();

    // ---- Compute: 4-slot ring over disparity (slot = w index & 3) ----
    float4 ra[4], rb[4];
    #pragma unroll
    for (int j = 0; j < 4; ++j) {
        ra[j] = *(const float4*)(rS + sw_off(w0 + j, 0));
        rb[j] = *(const float4*)(rS + sw_off(w0 + j, 16));
    }

    float* op = out + (((n * G + g) * DISP) * H + h) * W + w0;

    if (w0 >= DISP) {
        // Fast path (tid >= 12): unconditional ring refill, no predicates.
        #pragma unroll 4
        for (int d = 0; d < DISP; ++d) {
            const int e  = d & 3;
            const int sn = (4 - e) & 3;          // slot of new position w0-d
            if (d > 0) {
                const int wn = w0 - d;
                ra[sn] = *(const float4*)(rS + sw_off(wn, 0));
                rb[sn] = *(const float4*)(rS + sw_off(wn, 16));
            }
            float4 o;
            o.x = DOT(0, (0 - e) & 3) * 0.125f;
            o.y = DOT(1, (1 - e) & 3) * 0.125f;
            o.z = DOT(2, (2 - e) & 3) * 0.125f;
            o.w = DOT(3, (3 - e) & 3) * 0.125f;
            __stcs((float4*)(op + d * HW), o);
        }
    } else {
        #pragma unroll 4
        for (int d = 0; d < DISP; ++d) {
            const int e  = d & 3;
            const int sn = (4 - e) & 3;
            const int wn = w0 - d;
            if (d > 0 && wn >= 0) {
                ra[sn] = *(const float4*)(rS + sw_off(wn, 0));
                rb[sn] = *(const float4*)(rS + sw_off(wn, 16));
            }
            float4 o;
            o.x = (w0 + 0 >= d) ? DOT(0, (0 - e) & 3) * 0.125f : 1.0f;
            o.y = (w0 + 1 >= d) ? DOT(1, (1 - e) & 3) * 0.125f : 1.0f;
            o.z = (w0 + 2 >= d) ? DOT(2, (2 - e) & 3) * 0.125f : 1.0f;
            o.w = (w0 + 3 >= d) ? DOT(3, (3 - e) & 3) * 0.125f : 1.0f;
            __stcs((float4*)(op + d * HW), o);
        }
    }
}

extern "C" void kernel_launch(void* const* d_in, const int* in_sizes, int n_in,
                              void* d_out, int out_size) {
    const float* l = (const float*)d_in[0];
    const float* r = (const float*)d_in[1];
    float* out = (float*)d_out;

    dim3 grid(H, NN, G);                 // 5120 CTAs: (h, n, group)
    gwc_kernel<<<grid, 80>>>(l, r, out);
}

// round 10
// speedup vs baseline: 3.1735x; 3.1735x over previous
#include <cuda_runtime.h>

#define NN 4
#define C  64
#define H  160
#define W  320
#define DISP 48
#define G  8
#define HW (H*W)
#define ROWB 32                        // 8 floats per w position (one group)
#define SMEM_BYTES (W * ROWB)          // 10KB

// XOR swizzle, 16B chunks, 32B rows (R6-proven conflict-free for lanes
// stepping w by 2 on loads and w by 1 on staging stores).
__device__ __forceinline__ unsigned sw_off(int w, int colbyte) {
    unsigned off = (unsigned)(w * ROWB + colbyte);
    off ^= (((unsigned)w >> 1) & 7u) << 4;
    return off;
}

#define DOT8(lw, a, b)                                              \
    ((lw[0]*(a).x + lw[1]*(a).y + lw[2]*(a).z + lw[3]*(a).w) +      \
     (lw[4]*(b).x + lw[5]*(b).y + lw[6]*(b).z + lw[7]*(b).w))

// Load the 8 channels at position w (clamped to 0) as two float4s.
// Second chunk address = first ^ 16 (bit4 of w*32 is 0; key XOR commutes).
#define LDPOS(wpos, a, b) do {                                      \
    int _w = (wpos); _w = _w < 0 ? 0 : _w;                          \
    unsigned _o = sw_off(_w, 0);                                    \
    (a) = *(const float4*)(rS + _o);                                \
    (b) = *(const float4*)(rS + (_o ^ 16u));                        \
} while (0)

__global__ __launch_bounds__(160, 6)
void gwc_kernel(const float* __restrict__ lg,
                const float* __restrict__ rg,
                float* __restrict__ out) {
    __shared__ __align__(16) char rS[SMEM_BYTES];

    const int h   = blockIdx.x;
    const int n   = blockIdx.y;
    const int g   = blockIdx.z;
    const int tid = threadIdx.x;
    const int w0  = tid * 2;             // this thread's 2 output columns

    // ---- l loads first: 8 coalesced LDG.64 ----
    const float* lp = lg + ((n * C + g * 8) * H + h) * W + w0;
    float lwA[8], lwB[8];
    #pragma unroll
    for (int c = 0; c < 8; ++c) {
        float2 v = *(const float2*)(lp + c * HW);
        lwA[c] = v.x; lwB[c] = v.y;
    }

    // ---- Stage this group's 8 r channels, transposed [w][c] (R6 layout) ----
    {
        const float* rbase = rg + ((n * C + g * 8) * H + h) * W;
        float4 rv[4];
        int ws[4];
        #pragma unroll
        for (int k = 0; k < 4; ++k) {
            int i  = tid + k * 160;
            int w  = i % W;
            int c4 = (i / W) * 4;        // 0 or 4
            int gb = c4 * HW + w;
            ws[k] = (int)sw_off(w, c4 * 4);
            rv[k].x = rbase[gb];
            rv[k].y = rbase[gb + HW];
            rv[k].z = rbase[gb + 2 * HW];
            rv[k].w = rbase[gb + 3 * HW];
        }
        #pragma unroll
        for (int k = 0; k < 4; ++k)
            *(float4*)(rS + ws[k]) = rv[k];
    }
    __syncthreads();

    // ---- Compute with distance-1 LDS prefetch.
    // Parity slots: slot p holds the r-position with (pos & 1) == p.
    // (w0 is even: at disparity d, output x uses parity d&1, y uses 1-(d&1).)
    float4 ra0, rb0, ra1, rb1, pa, pb;
    LDPOS(w0,     ra0, rb0);             // parity 0, used at d=0 (x), d=1 (y)
    LDPOS(w0 + 1, ra1, rb1);             // parity 1, used at d=0 (y)
    LDPOS(w0 - 1, pa, pb);               // -> parity 1 slot for d=1

    float* op = out + (((n * G + g) * DISP) * H + h) * W + w0;

    if (w0 >= DISP) {
        #pragma unroll 4
        for (int d2 = 0; d2 < DISP; d2 += 2) {
            float2 o;
            o.x = DOT8(lwA, ra0, rb0) * 0.125f;     // pos w0-d2   (par 0)
            o.y = DOT8(lwB, ra1, rb1) * 0.125f;     // pos w0+1-d2 (par 1)
            __stcs((float2*)(op + d2 * HW), o);

            ra1 = pa; rb1 = pb;                     // commit pos w0-d2-1
            LDPOS(w0 - d2 - 2, pa, pb);             // prefetch par-0 for d2+2

            o.x = DOT8(lwA, ra1, rb1) * 0.125f;     // pos w0-d2-1 (par 1)
            o.y = DOT8(lwB, ra0, rb0) * 0.125f;     // pos w0-d2   (par 0)
            __stcs((float2*)(op + (d2 + 1) * HW), o);

            ra0 = pa; rb0 = pb;                     // commit pos w0-d2-2
            LDPOS(w0 - d2 - 3, pa, pb);             // prefetch par-1 for d2+3
        }
    } else {
        #pragma unroll 4
        for (int d2 = 0; d2 < DISP; d2 += 2) {
            float2 o;
            o.x = (w0     >= d2) ? DOT8(lwA, ra0, rb0) * 0.125f : 1.0f;
            o.y = (w0 + 1 >= d2) ? DOT8(lwB, ra1, rb1) * 0.125f : 1.0f;
            __stcs((float2*)(op + d2 * HW), o);

            ra1 = pa; rb1 = pb;
            LDPOS(w0 - d2 - 2, pa, pb);

            o.x = (w0     >= d2 + 1) ? DOT8(lwA, ra1, rb1) * 0.125f : 1.0f;
            o.y = (w0 + 1 >= d2 + 1) ? DOT8(lwB, ra0, rb0) * 0.125f : 1.0f;
            __stcs((float2*)(op + (d2 + 1) * HW), o);

            ra0 = pa; rb0 = pb;
            LDPOS(w0 - d2 - 3, pa, pb);
        }
    }
}

extern "C" void kernel_launch(void* const* d_in, const int* in_sizes, int n_in,
                              void* d_out, int out_size) {
    const float* l = (const float*)d_in[0];
    const float* r = (const float*)d_in[1];
    float* out = (float*)d_out;

    dim3 grid(H, NN, G);                 // 5120 CTAs: (h, n, group)
    gwc_kernel<<<grid, 160>>>(l, r, out);
}

// round 11
// speedup vs baseline: 3.4168x; 1.0767x over previous
#include <cuda_runtime.h>

#define NN 4
#define C  64
#define H  160
#define W  320
#define DISP 48
#define G  8
#define HW (H*W)
#define ROWB 32                        // 8 floats per w position (one group)
#define SMEM_BYTES (W * ROWB)          // 10KB

// XOR swizzle, 16B chunks, 32B rows (R6-proven conflict-free: compute lanes
// step w by 2, staging stores step w by 1).
__device__ __forceinline__ unsigned sw_off(int w, int colbyte) {
    unsigned off = (unsigned)(w * ROWB + colbyte);
    off ^= (((unsigned)w >> 1) & 7u) << 4;
    return off;
}

// dot, two independent 4-FFMA chains + add (l pre-scaled by 1/8).
#define DOT(lw, s)                                                      \
    ((lw[0]*ra[s].x + lw[1]*ra[s].y + lw[2]*ra[s].z + lw[3]*ra[s].w) +  \
     (lw[4]*rb[s].x + lw[5]*rb[s].y + lw[6]*rb[s].z + lw[7]*rb[s].w))

__global__ __launch_bounds__(160, 7)
void gwc_kernel(const float* __restrict__ lg,
                const float* __restrict__ rg,
                float* __restrict__ out) {
    __shared__ __align__(16) char rS[SMEM_BYTES];

    const int h   = blockIdx.x;
    const int n   = blockIdx.y;
    const int g   = blockIdx.z;
    const int tid = threadIdx.x;
    const int w0  = tid * 2;             // this thread's 2 output columns

    // ---- l loads first: 8 coalesced LDG.64; pre-scale by 1/8 ----
    const float* lp = lg + ((n * C + g * 8) * H + h) * W + w0;
    float lwA[8], lwB[8];
    #pragma unroll
    for (int c = 0; c < 8; ++c) {
        float2 v = *(const float2*)(lp + c * HW);
        lwA[c] = v.x * 0.125f; lwB[c] = v.y * 0.125f;
    }

    // ---- Stage this group's 8 r channels, transposed [w][c], swizzled ----
    {
        const float* rbase = rg + ((n * C + g * 8) * H + h) * W;
        float4 rv[4];
        int ws[4];
        #pragma unroll
        for (int k = 0; k < 4; ++k) {
            int i  = tid + k * 160;
            int w  = i % W;
            int c4 = (i / W) * 4;        // 0 or 4
            int gb = c4 * HW + w;
            ws[k] = (int)sw_off(w, c4 * 4);
            rv[k].x = rbase[gb];
            rv[k].y = rbase[gb + HW];
            rv[k].z = rbase[gb + 2 * HW];
            rv[k].w = rbase[gb + 3 * HW];
        }
        #pragma unroll
        for (int k = 0; k < 4; ++k)
            *(float4*)(rS + ws[k]) = rv[k];
    }
    __syncthreads();

    // ---- Compute: 2-slot sliding window over disparity ----
    float4 ra[2], rb[2];                 // slot p = parity of r position
    {
        unsigned o0 = sw_off(w0, 0);
        ra[0] = *(const float4*)(rS + o0);
        rb[0] = *(const float4*)(rS + (o0 ^ 16u));
        unsigned o1 = sw_off(w0 + 1, 0);
        ra[1] = *(const float4*)(rS + o1);
        rb[1] = *(const float4*)(rS + (o1 ^ 16u));
    }

    float* op = out + (((n * G + g) * DISP) * H + h) * W + w0;

    if (w0 >= DISP) {
        #pragma unroll 4
        for (int d2 = 0; d2 < DISP; d2 += 2) {
            // d = d2 (even): output x parity 0, y parity 1
            if (d2 > 0) {
                unsigned o = sw_off(w0 - d2, 0);
                ra[0] = *(const float4*)(rS + o);
                rb[0] = *(const float4*)(rS + (o ^ 16u));
            }
            float2 o01;
            o01.x = DOT(lwA, 0);
            o01.y = DOT(lwB, 1);
            __stcs((float2*)op, o01);

            // d = d2+1 (odd): new position w0-d2-1 has parity 1
            {
                unsigned o = sw_off(w0 - d2 - 1, 0);
                ra[1] = *(const float4*)(rS + o);
                rb[1] = *(const float4*)(rS + (o ^ 16u));
            }
            o01.x = DOT(lwA, 1);
            o01.y = DOT(lwB, 0);
            __stcs((float2*)(op + HW), o01);

            op += 2 * HW;
        }
    } else {
        #pragma unroll 4
        for (int d2 = 0; d2 < DISP; d2 += 2) {
            const int wn0 = w0 - d2;
            if (d2 > 0 && wn0 >= 0) {
                unsigned o = sw_off(wn0, 0);
                ra[0] = *(const float4*)(rS + o);
                rb[0] = *(const float4*)(rS + (o ^ 16u));
            }
            float2 o01;
            o01.x = (w0     >= d2) ? DOT(lwA, 0) : 1.0f;
            o01.y = (w0 + 1 >= d2) ? DOT(lwB, 1) : 1.0f;
            __stcs((float2*)op, o01);

            const int wn1 = w0 - d2 - 1;
            if (wn1 >= 0) {
                unsigned o = sw_off(wn1, 0);
                ra[1] = *(const float4*)(rS + o);
                rb[1] = *(const float4*)(rS + (o ^ 16u));
            }
            o01.x = (w0     >= d2 + 1) ? DOT(lwA, 1) : 1.0f;
            o01.y = (w0 + 1 >= d2 + 1) ? DOT(lwB, 0) : 1.0f;
            __stcs((float2*)(op + HW), o01);

            op += 2 * HW;
        }
    }
}

extern "C" void kernel_launch(void* const* d_in, const int* in_sizes, int n_in,
                              void* d_out, int out_size) {
    const float* l = (const float*)d_in[0];
    const float* r = (const float*)d_in[1];
    float* out = (float*)d_out;

    dim3 grid(H, NN, G);                 // 5120 CTAs: (h, n, group)
    gwc_kernel<<<grid, 160>>>(l, r, out);
}